// round 3
// baseline (speedup 1.0000x reference)
#include <cuda_runtime.h>
#include <cuda_bf16.h>

#define NN 262144
#define DD 1024
#define GG 1024
#define NA 17
#define EPS 1e-5f
#define SPLITK 8

// ---------------- scratch (device globals; no allocation allowed) -------------
__device__ int   d_starts[GG + 1];
__device__ float d_stats[GG * 56];                 // a0[17], a1[17], c2[17], n0, n1
__device__ float d_pooled[GG * DD];                // 4 MB
__device__ float d_part[SPLITK * GG * (DD / 2)];   // 16 MB split-K partials (reused)
__device__ float d_r0[GG * (DD / 2)];              // relu(fc0)+bias (pre-BN)
__device__ float d_r1[GG * (DD / 4)];              // relu(fc1)+bias (pre-BN)
__device__ float d_bnsum[8 * (DD / 2)];
__device__ float d_bnsq[8 * (DD / 2)];
__device__ float d_scale[DD / 2];                  // rstd*g
__device__ float d_shift[DD / 2];                  // b - mean*rstd*g

// ---------------- K1: segment starts via binary search ------------------------
__global__ void k_find_starts(const int* __restrict__ batch) {
    int i = blockIdx.x * blockDim.x + threadIdx.x;
    if (i > GG) return;
    int lo = 0, hi = NN;
    while (lo < hi) {
        int mid = (lo + hi) >> 1;
        if (batch[mid] < i) lo = mid + 1; else hi = mid;
    }
    d_starts[i] = lo;
}

// ---------------- K2: per-graph attr stats ------------------------------------
__global__ void k_stats(const float* __restrict__ attr, const int* __restrict__ ntype) {
    int gph = blockIdx.x;
    int s0 = d_starts[gph], s1 = d_starts[gph + 1];

    float a0[NA], a1[NA], c2[NA];
    #pragma unroll
    for (int k = 0; k < NA; k++) { a0[k] = 0.f; a1[k] = 0.f; c2[k] = 0.f; }
    float n0 = 0.f, n1 = 0.f;

    for (int r = s0 + threadIdx.x; r < s1; r += blockDim.x) {
        int t = ntype[r];
        const float* ar = attr + (long)r * NA;
        float av[NA];
        #pragma unroll
        for (int k = 0; k < NA; k++) av[k] = ar[k];
        if (t == 0) {
            n0 += 1.f;
            #pragma unroll
            for (int k = 0; k < NA; k++) a0[k] += av[k];
        } else if (t == 1) {
            n1 += 1.f;
            #pragma unroll
            for (int k = 0; k < NA; k++) a1[k] += av[k];
        } else if (t == 2) {
            int idx = (int)av[0];
            idx = idx < 0 ? 0 : (idx > NA - 1 ? NA - 1 : idx);
            #pragma unroll
            for (int k = 0; k < NA; k++) c2[k] += (k == idx) ? 1.f : 0.f;
        }
    }

    __shared__ float s_acc[56];
    for (int j = threadIdx.x; j < 56; j += blockDim.x) s_acc[j] = 0.f;
    __syncthreads();

    int lane = threadIdx.x & 31;
    #pragma unroll
    for (int k = 0; k < NA; k++) {
        float v = a0[k];
        #pragma unroll
        for (int o = 16; o; o >>= 1) v += __shfl_xor_sync(0xffffffffu, v, o);
        if (lane == 0) atomicAdd(&s_acc[k], v);
        v = a1[k];
        #pragma unroll
        for (int o = 16; o; o >>= 1) v += __shfl_xor_sync(0xffffffffu, v, o);
        if (lane == 0) atomicAdd(&s_acc[NA + k], v);
        v = c2[k];
        #pragma unroll
        for (int o = 16; o; o >>= 1) v += __shfl_xor_sync(0xffffffffu, v, o);
        if (lane == 0) atomicAdd(&s_acc[2 * NA + k], v);
    }
    {
        float v = n0;
        #pragma unroll
        for (int o = 16; o; o >>= 1) v += __shfl_xor_sync(0xffffffffu, v, o);
        if (lane == 0) atomicAdd(&s_acc[51], v);
        v = n1;
        #pragma unroll
        for (int o = 16; o; o >>= 1) v += __shfl_xor_sync(0xffffffffu, v, o);
        if (lane == 0) atomicAdd(&s_acc[52], v);
    }
    __syncthreads();
    for (int j = threadIdx.x; j < 56; j += blockDim.x) d_stats[gph * 56 + j] = s_acc[j];
}

// ---------------- K3: segment sum of x + fused tiny emb GEMM + mean ----------
// grid = 2*GG: block b handles graph b>>1, column half b&1 (128 float4 cols).
// 256 threads: lower/upper 128 threads take even/odd rows, combined via smem.
__global__ void k_pool(const float* __restrict__ x,
                       const float* __restrict__ netW, const float* __restrict__ netb,
                       const float* __restrict__ devW, const float* __restrict__ devb,
                       const float* __restrict__ pinE) {
    int gph = blockIdx.x >> 1;
    int half = blockIdx.x & 1;
    int s0 = d_starts[gph], s1 = d_starts[gph + 1];

    __shared__ float st[56];
    for (int j = threadIdx.x; j < 56; j += 256) st[j] = d_stats[gph * 56 + j];
    __syncthreads();

    int c4 = half * 128 + (threadIdx.x & 127);
    int par = threadIdx.x >> 7;
    const float4* x4 = (const float4*)x;
    float4 acc = make_float4(0.f, 0.f, 0.f, 0.f);

    #pragma unroll 4
    for (int r = s0 + par; r < s1; r += 2) {
        float4 v = x4[(long)r * 256 + c4];
        acc.x += v.x; acc.y += v.y; acc.z += v.z; acc.w += v.w;
    }

    __shared__ float4 s_up[128];
    if (par == 1) s_up[threadIdx.x & 127] = acc;
    __syncthreads();
    if (par == 0) {
        float4 u = s_up[threadIdx.x];
        acc.x += u.x; acc.y += u.y; acc.z += u.z; acc.w += u.w;

        const float4* nW4 = (const float4*)netW;
        const float4* dW4 = (const float4*)devW;
        const float4* pE4 = (const float4*)pinE;
        float4 e = make_float4(0.f, 0.f, 0.f, 0.f);
        #pragma unroll
        for (int k = 0; k < NA; k++) {
            float4 wn = nW4[k * 256 + c4];
            float4 wd = dW4[k * 256 + c4];
            float4 wp = pE4[k * 256 + c4];
            float a0 = st[k], a1 = st[NA + k], cc = st[2 * NA + k];
            e.x += a0 * wn.x + a1 * wd.x + cc * wp.x;
            e.y += a0 * wn.y + a1 * wd.y + cc * wp.y;
            e.z += a0 * wn.z + a1 * wd.z + cc * wp.z;
            e.w += a0 * wn.w + a1 * wd.w + cc * wp.w;
        }
        float n0 = st[51], n1 = st[52];
        float4 nb = ((const float4*)netb)[c4];
        float4 db = ((const float4*)devb)[c4];
        e.x += n0 * nb.x + n1 * db.x;
        e.y += n0 * nb.y + n1 * db.y;
        e.z += n0 * nb.z + n1 * db.z;
        e.w += n0 * nb.w + n1 * db.w;

        float inv = 1.f / fmaxf((float)(s1 - s0), 1.f);
        float4 o;
        o.x = (acc.x + e.x) * inv;
        o.y = (acc.y + e.y) * inv;
        o.z = (acc.z + e.z) * inv;
        o.w = (acc.w + e.w) * inv;
        ((float4*)d_pooled)[(long)gph * 256 + c4] = o;
    }
}

// ---------------- K4: split-K GEMM, 128x64 tile, 8x4/thread, double-buffered --
// If useBN != 0, applies A' = A*scale[k] + shift[k] on the fly (fused BN).
__global__ void k_gemm_splitk(const float* __restrict__ A, const float* __restrict__ W,
                              float* __restrict__ part, int M, int N, int K, int kChunk,
                              int useBN) {
    __shared__ float As[16][128];
    __shared__ float Bs[16][68];
    int tid = threadIdx.x;
    int tx = tid & 15;
    int ty = tid >> 4;
    int n0 = blockIdx.x * 64, m0 = blockIdx.y * 128;
    int k0 = blockIdx.z * kChunk;
    int kend = k0 + kChunk;
    float acc[8][4] = {};

    // prefetch registers
    float ra[8], rb[4];
    int am[8], ak[8], bk[4], bn[4];
    #pragma unroll
    for (int i = 0; i < 8; i++) { int idx = tid + i * 256; am[i] = idx >> 4; ak[i] = idx & 15; }
    #pragma unroll
    for (int i = 0; i < 4; i++) { int idx = tid + i * 256; bk[i] = idx >> 6; bn[i] = idx & 63; }

    // load first tile
    #pragma unroll
    for (int i = 0; i < 8; i++) {
        float v = A[(long)(m0 + am[i]) * K + k0 + ak[i]];
        if (useBN) v = v * d_scale[k0 + ak[i]] + d_shift[k0 + ak[i]];
        ra[i] = v;
    }
    #pragma unroll
    for (int i = 0; i < 4; i++) rb[i] = W[(long)(k0 + bk[i]) * N + n0 + bn[i]];

    for (int kb = k0; kb < kend; kb += 16) {
        #pragma unroll
        for (int i = 0; i < 8; i++) As[ak[i]][am[i]] = ra[i];
        #pragma unroll
        for (int i = 0; i < 4; i++) Bs[bk[i]][bn[i]] = rb[i];
        __syncthreads();

        int kn = kb + 16;
        if (kn < kend) {
            #pragma unroll
            for (int i = 0; i < 8; i++) {
                float v = A[(long)(m0 + am[i]) * K + kn + ak[i]];
                if (useBN) v = v * d_scale[kn + ak[i]] + d_shift[kn + ak[i]];
                ra[i] = v;
            }
            #pragma unroll
            for (int i = 0; i < 4; i++) rb[i] = W[(long)(kn + bk[i]) * N + n0 + bn[i]];
        }

        #pragma unroll
        for (int kk = 0; kk < 16; kk++) {
            float4 a0 = *(const float4*)&As[kk][ty * 8];
            float4 a1 = *(const float4*)&As[kk][ty * 8 + 4];
            float4 b  = *(const float4*)&Bs[kk][tx * 4];
            float av[8] = {a0.x, a0.y, a0.z, a0.w, a1.x, a1.y, a1.z, a1.w};
            float bv[4] = {b.x, b.y, b.z, b.w};
            #pragma unroll
            for (int i = 0; i < 8; i++)
                #pragma unroll
                for (int j = 0; j < 4; j++)
                    acc[i][j] += av[i] * bv[j];
        }
        __syncthreads();
    }
    float* dst = part + (long)blockIdx.z * M * N;
    #pragma unroll
    for (int i = 0; i < 8; i++) {
        int m = m0 + ty * 8 + i;
        #pragma unroll
        for (int j = 0; j < 4; j++)
            dst[(long)m * N + n0 + tx * 4 + j] = acc[i][j];
    }
}

// ---------------- K5: combine split-K + bias + relu + column stats -----------
// grid (N/64, 8): block handles 64 cols x 128 rows. 256 thr: tx 16 f4-cols, ty 16 rows.
__global__ void k_combine_stats(const float* __restrict__ part, const float* __restrict__ bias,
                                float* __restrict__ out, int MN, int N) {
    int tx = threadIdx.x & 15;
    int ty = threadIdx.x >> 4;
    int c4 = blockIdx.x * 16 + tx;          // float4 column
    int rbase = blockIdx.y * 128;
    int N4 = N >> 2;

    float4 bb = ((const float4*)bias)[c4];
    float4 sum = make_float4(0.f, 0.f, 0.f, 0.f);
    float4 sq  = make_float4(0.f, 0.f, 0.f, 0.f);

    for (int r = rbase + ty; r < rbase + 128; r += 16) {
        float4 v = make_float4(0.f, 0.f, 0.f, 0.f);
        long base = (long)r * N4 + c4;
        #pragma unroll
        for (int s = 0; s < SPLITK; s++) {
            float4 p = ((const float4*)part)[(long)s * (MN >> 2) + base];
            v.x += p.x; v.y += p.y; v.z += p.z; v.w += p.w;
        }
        v.x = fmaxf(v.x + bb.x, 0.f);
        v.y = fmaxf(v.y + bb.y, 0.f);
        v.z = fmaxf(v.z + bb.z, 0.f);
        v.w = fmaxf(v.w + bb.w, 0.f);
        ((float4*)out)[base] = v;
        sum.x += v.x; sum.y += v.y; sum.z += v.z; sum.w += v.w;
        sq.x += v.x * v.x; sq.y += v.y * v.y; sq.z += v.z * v.z; sq.w += v.w * v.w;
    }

    __shared__ float4 ssum[16][16], ssq[16][16];
    ssum[ty][tx] = sum; ssq[ty][tx] = sq;
    __syncthreads();
    if (ty == 0) {
        float4 S = ssum[0][tx], Q = ssq[0][tx];
        #pragma unroll
        for (int j = 1; j < 16; j++) {
            float4 s2 = ssum[j][tx], q2 = ssq[j][tx];
            S.x += s2.x; S.y += s2.y; S.z += s2.z; S.w += s2.w;
            Q.x += q2.x; Q.y += q2.y; Q.z += q2.z; Q.w += q2.w;
        }
        int col = c4 * 4;
        *(float4*)&d_bnsum[blockIdx.y * N + col] = S;
        *(float4*)&d_bnsq[blockIdx.y * N + col] = Q;
    }
}

// ---------------- K6: finalize BN -> scale/shift ------------------------------
__global__ void k_bnfinal(const float* __restrict__ g, const float* __restrict__ b, int N) {
    int c = blockIdx.x * blockDim.x + threadIdx.x;
    if (c >= N) return;
    float s = 0.f, q = 0.f;
    #pragma unroll
    for (int ch = 0; ch < 8; ch++) { s += d_bnsum[ch * N + c]; q += d_bnsq[ch * N + c]; }
    float m = s / (float)GG;
    float var = q / (float)GG - m * m;
    float rs = rsqrtf(var + EPS);
    float sc = rs * g[c];
    d_scale[c] = sc;
    d_shift[c] = b[c] - m * sc;
}

// ---------------- K7: fc2 dot(256) with fused BN + output assembly -----------
__global__ void k_head_out(const float* __restrict__ R1, const float* __restrict__ w,
                           const float* __restrict__ b, const float* __restrict__ y_reg,
                           float* __restrict__ out, int out_size) {
    int warp = (blockIdx.x * blockDim.x + threadIdx.x) >> 5;
    int lane = threadIdx.x & 31;
    if (warp >= GG) return;
    float s = 0.f;
    #pragma unroll
    for (int k = lane; k < DD / 4; k += 32) {
        float h = R1[(long)warp * (DD / 4) + k] * d_scale[k] + d_shift[k];
        s += h * w[k];
    }
    #pragma unroll
    for (int o = 16; o; o >>= 1) s += __shfl_xor_sync(0xffffffffu, s, o);
    if (lane == 0) {
        out[warp] = s + b[0];
        if (out_size >= 2 * GG) out[GG + warp] = y_reg[warp];
    }
}

// ---------------- launch ------------------------------------------------------
extern "C" void kernel_launch(void* const* d_in, const int* in_sizes, int n_in,
                              void* d_out, int out_size) {
    const float* x        = (const float*)d_in[0];
    const float* nattr    = (const float*)d_in[1];
    const int*   ntype    = (const int*)d_in[2];
    const int*   batch    = (const int*)d_in[3];
    const float* y_reg    = (const float*)d_in[4];
    const float* net_W    = (const float*)d_in[5];
    const float* net_b    = (const float*)d_in[6];
    const float* dev_W    = (const float*)d_in[7];
    const float* dev_b    = (const float*)d_in[8];
    const float* pin_emb  = (const float*)d_in[9];
    const float* fc0_W    = (const float*)d_in[10];
    const float* fc0_b    = (const float*)d_in[11];
    const float* fc1_W    = (const float*)d_in[12];
    const float* fc1_b    = (const float*)d_in[13];
    const float* fc2_W    = (const float*)d_in[14];
    const float* fc2_b    = (const float*)d_in[15];
    const float* bn0_g    = (const float*)d_in[16];
    const float* bn0_b    = (const float*)d_in[17];
    const float* bn1_g    = (const float*)d_in[18];
    const float* bn1_b    = (const float*)d_in[19];
    float* out = (float*)d_out;

    float *p_pooled, *p_part, *p_r0, *p_r1;
    cudaGetSymbolAddress((void**)&p_pooled, d_pooled);
    cudaGetSymbolAddress((void**)&p_part, d_part);
    cudaGetSymbolAddress((void**)&p_r0, d_r0);
    cudaGetSymbolAddress((void**)&p_r1, d_r1);

    const int N0 = DD / 2;   // 512
    const int N1 = DD / 4;   // 256
    const int MN0 = GG * N0;
    const int MN1 = GG * N1;

    k_find_starts<<<(GG + 1 + 255) / 256, 256>>>(batch);
    k_stats<<<GG, 128>>>(nattr, ntype);
    k_pool<<<2 * GG, 256>>>(x, net_W, net_b, dev_W, dev_b, pin_emb);

    // fc0: 1024x512x1024, split-K 8
    k_gemm_splitk<<<dim3(N0 / 64, GG / 128, SPLITK), 256>>>(p_pooled, fc0_W, p_part, GG, N0, DD, DD / SPLITK, 0);
    k_combine_stats<<<dim3(N0 / 64, 8), 256>>>(p_part, fc0_b, p_r0, MN0, N0);
    k_bnfinal<<<(N0 + 255) / 256, 256>>>(bn0_g, bn0_b, N0);

    // fc1: 1024x256x512, split-K 8, BN(layer0) fused into A loads
    k_gemm_splitk<<<dim3(N1 / 64, GG / 128, SPLITK), 256>>>(p_r0, fc1_W, p_part, GG, N1, N0, N0 / SPLITK, 1);
    k_combine_stats<<<dim3(N1 / 64, 8), 256>>>(p_part, fc1_b, p_r1, MN1, N1);
    k_bnfinal<<<(N1 + 255) / 256, 256>>>(bn1_g, bn1_b, N1);

    k_head_out<<<(GG * 32 + 255) / 256, 256>>>(p_r1, fc2_W, fc2_b, y_reg, out, out_size);
}